// round 4
// baseline (speedup 1.0000x reference)
#include <cuda_runtime.h>
#include <cstdint>
#include <cstddef>

#define BSZ   64
#define NI    2048
#define DI    8
#define NO    32
#define DOUT  16

#define BT    32
#define NCH   4
#define NTHREADS 512
#define GRID  148
#define ITEMS_PER_BT (NI / NCH)            // 512
#define N_ITEMS (ITEMS_PER_BT * 2)         // 1024

typedef unsigned long long ull;

__device__ float g_s[BSZ * NO * DOUT];           // zero at entry (squash re-zeros)
__device__ float g_v[BSZ * NO * DOUT];
__device__ float g_blog[(size_t)BSZ * NI * NO];  // 16 MB logits
__device__ unsigned g_ctr;                       // last-CTA ticket (reset each launch)

static __device__ __forceinline__ ull pack2(float lo, float hi) {
    ull r; asm("mov.b64 %0,{%1,%2};" : "=l"(r) : "f"(lo), "f"(hi)); return r;
}
static __device__ __forceinline__ float2 unpk(ull v) {
    float2 r; asm("mov.b64 {%0,%1},%2;" : "=f"(r.x), "=f"(r.y) : "l"(v)); return r;
}
static __device__ __forceinline__ ull fma2(ull a, ull b, ull c) {
    ull d; asm("fma.rn.f32x2 %0,%1,%2,%3;" : "=l"(d) : "l"(a), "l"(b), "l"(c)); return d;
}
static __device__ __forceinline__ ull mul2(ull a, ull b) {
    ull d; asm("mul.rn.f32x2 %0,%1,%2;" : "=l"(d) : "l"(a), "l"(b)); return d;
}

// Squash executed by the last CTA of each pass: v = s*||s||/(1+||s||^2), zero g_s.
static __device__ __forceinline__ void do_squash(float* __restrict__ dst)
{
#pragma unroll
    for (int rr = 0; rr < 4; rr++) {
        int row = threadIdx.x * 4 + rr;            // 2048 rows of 16
        const float* p = g_s + row * 16;
        float4 a = *(const float4*)(p + 0);
        float4 b = *(const float4*)(p + 4);
        float4 c = *(const float4*)(p + 8);
        float4 d = *(const float4*)(p + 12);
        float sq = a.x*a.x + a.y*a.y + a.z*a.z + a.w*a.w
                 + b.x*b.x + b.y*b.y + b.z*b.z + b.w*b.w
                 + c.x*c.x + c.y*c.y + c.z*c.z + c.w*c.w
                 + d.x*d.x + d.y*d.y + d.z*d.z + d.w*d.w;
        float f = sqrtf(sq) / (1.0f + sq);
        float* q = dst + row * 16;
        *(float4*)(q + 0)  = make_float4(a.x*f, a.y*f, a.z*f, a.w*f);
        *(float4*)(q + 4)  = make_float4(b.x*f, b.y*f, b.z*f, b.w*f);
        *(float4*)(q + 8)  = make_float4(c.x*f, c.y*f, c.z*f, c.w*f);
        *(float4*)(q + 12) = make_float4(d.x*f, d.y*f, d.z*f, d.w*f);
        float4 z = make_float4(0.f, 0.f, 0.f, 0.f);
        float* zp = g_s + row * 16;
        *(float4*)(zp + 0) = z; *(float4*)(zp + 4) = z;
        *(float4*)(zp + 8) = z; *(float4*)(zp + 12) = z;
    }
}

// W SMEM layout per n (16 KB), pair-interleaved over d for fma2 operands:
//   16B unit at (o*32 + dp*4 + ip), swizzled by XOR of o into the low 5 unit bits
//   (byte ^ (o<<4)) -> conflict-free LDS.128 for both staging and compute.
template <int PASS>
__global__ void __launch_bounds__(NTHREADS, 1)
caps_pass(const float* __restrict__ X, const float* __restrict__ W,
          float* __restrict__ vout)
{
    extern __shared__ char sm[];
    char*   w_s = sm;                                  // NCH*16384 = 65536 B
    float2* x_d = (float2*)(sm + 65536);               // 8192 B (x dup pairs)
    float*  v_s = (float*)(sm + 65536 + 8192);         // 65536 B
    float*  red = (float*)(sm + 65536 + 8192 + 65536); // 512 B
    __shared__ int s_last;

    const int tid = threadIdx.x;
    const int wg  = tid >> 7;
    const int wt  = tid & 127;
    const int o   = wt >> 2;
    const int dg  = wt & 3;
    const int wiw = (wt >> 5) & 3;
    const unsigned xo = (unsigned)o << 4;

    // staging coords (one 8-float unit per thread per n)
    const int so  = tid >> 4;
    const int sdp = (tid >> 1) & 7;
    const int siq = tid & 1;
    const unsigned sxo = (unsigned)so << 4;

    const ull Z = pack2(0.f, 0.f);
    ull s0[8], s1[8];
#pragma unroll
    for (int b = 0; b < 8; b++) { s0[b] = Z; s1[b] = Z; }

    int cur_bt = -1;

    for (int it = blockIdx.x; it < N_ITEMS; it += GRID) {
        const int btile = it >> 9;
        const int n0    = (it & (ITEMS_PER_BT - 1)) * NCH;

        if (btile != cur_bt) {
            __syncthreads();                   // all done with v_s & prior buffers
            if (cur_bt >= 0) {
#pragma unroll
                for (int bi = 0; bi < 8; bi++) {
                    float* p = g_s + (size_t)(cur_bt * BT + wg * 8 + bi) * 512 + o * 16 + dg * 4;
                    float2 a = unpk(s0[bi]); float2 b = unpk(s1[bi]);
                    atomicAdd(p + 0, a.x); atomicAdd(p + 1, a.y);
                    atomicAdd(p + 2, b.x); atomicAdd(p + 3, b.y);
                    s0[bi] = Z; s1[bi] = Z;
                }
            }
            if (PASS > 0) {
#pragma unroll
                for (int k = 0; k < 8; k++) {
                    int f = k * 2048 + tid * 4;
                    *(float4*)(v_s + f) = *(const float4*)(g_v + (size_t)btile * BT * 512 + f);
                }
            }
            cur_bt = btile;
        } else {
            __syncthreads();                   // prior item done with w_s / x_d
        }

        // ---- stage W for NCH n's (coalesced read, swizzled pair-interleaved write) ----
#pragma unroll
        for (int nn = 0; nn < NCH; nn++) {
            const float* gw = W + (size_t)(n0 + nn) * 4096 + so * 128 + sdp * 16 + siq * 4;
            float4 a = *(const float4*)gw;        // d = 2*sdp
            float4 c = *(const float4*)(gw + 8);  // d = 2*sdp+1
            char* dst = w_s + nn * 16384 + so * 512;
            unsigned u = (unsigned)(sdp * 64 + siq * 32);
            *(float4*)(dst + (u ^ sxo))        = make_float4(a.x, c.x, a.y, c.y);
            *(float4*)(dst + ((u + 16) ^ sxo)) = make_float4(a.z, c.z, a.w, c.w);
        }
        // ---- stage x duplicated pairs: x_d[b*32 + nn*8 + i] = (x,x) ----
        {
            int f = tid * 2;
            int bb = f >> 5, rem = f & 31;
            float2 t2 = *(const float2*)(X + (size_t)(cur_bt * BT + bb) * (NI * DI) + n0 * DI + rem);
            x_d[f]     = make_float2(t2.x, t2.x);
            x_d[f + 1] = make_float2(t2.y, t2.y);
        }
        __syncthreads();

#pragma unroll 1
        for (int nn = 0; nn < NCH; nn++) {
            const int n = n0 + nn;

            ull w0[8], w1[8];
            const char* wb = w_s + nn * 16384 + o * 512;
#pragma unroll
            for (int ip = 0; ip < 4; ip++) {
                ulonglong2 uA = *(const ulonglong2*)(wb + ((unsigned)((dg * 2 + 0) * 64 + ip * 16) ^ xo));
                ulonglong2 uB = *(const ulonglong2*)(wb + ((unsigned)((dg * 2 + 1) * 64 + ip * 16) ^ xo));
                w0[2 * ip] = uA.x; w0[2 * ip + 1] = uA.y;
                w1[2 * ip] = uB.x; w1[2 * ip + 1] = uB.y;
            }

            if (PASS == 0) {
                const ull C = pack2(0.03125f, 0.03125f);
#pragma unroll
                for (int bi = 0; bi < 8; bi++) {
                    const ulonglong2* xq = (const ulonglong2*)(x_d + (wg * 8 + bi) * 32 + nn * 8);
                    ulonglong2 qa = xq[0];
                    ull h0 = fma2(w0[0], qa.x, mul2(w0[1], qa.y));
                    ull h1 = fma2(w1[0], qa.x, mul2(w1[1], qa.y));
                    ulonglong2 qb = xq[1];
                    h0 = fma2(w0[2], qb.x, h0); h1 = fma2(w1[2], qb.x, h1);
                    h0 = fma2(w0[3], qb.y, h0); h1 = fma2(w1[3], qb.y, h1);
                    ulonglong2 qc = xq[2];
                    h0 = fma2(w0[4], qc.x, h0); h1 = fma2(w1[4], qc.x, h1);
                    h0 = fma2(w0[5], qc.y, h0); h1 = fma2(w1[5], qc.y, h1);
                    ulonglong2 qd = xq[3];
                    h0 = fma2(w0[6], qd.x, h0); h1 = fma2(w1[6], qd.x, h1);
                    h0 = fma2(w0[7], qd.y, h0); h1 = fma2(w1[7], qd.y, h1);
                    s0[bi] = fma2(C, h0, s0[bi]);
                    s1[bi] = fma2(C, h1, s1[bi]);
                }
            } else {
#pragma unroll
                for (int g = 0; g < 2; g++) {
                    ull t0[4], t1[4];
#pragma unroll
                    for (int q = 0; q < 4; q++) {
                        const int bi = g * 4 + q, bloc = wg * 8 + bi;
                        const ulonglong2* xq = (const ulonglong2*)(x_d + bloc * 32 + nn * 8);
                        ulonglong2 qa = xq[0];
                        ull h0 = fma2(w0[0], qa.x, mul2(w0[1], qa.y));
                        ull h1 = fma2(w1[0], qa.x, mul2(w1[1], qa.y));
                        ulonglong2 qb = xq[1];
                        h0 = fma2(w0[2], qb.x, h0); h1 = fma2(w1[2], qb.x, h1);
                        h0 = fma2(w0[3], qb.y, h0); h1 = fma2(w1[3], qb.y, h1);
                        ulonglong2 qc = xq[2];
                        h0 = fma2(w0[4], qc.x, h0); h1 = fma2(w1[4], qc.x, h1);
                        h0 = fma2(w0[5], qc.y, h0); h1 = fma2(w1[5], qc.y, h1);
                        ulonglong2 qd = xq[3];
                        h0 = fma2(w0[6], qd.x, h0); h1 = fma2(w1[6], qd.x, h1);
                        h0 = fma2(w0[7], qd.y, h0); h1 = fma2(w1[7], qd.y, h1);

                        const ulonglong2 vv = *(const ulonglong2*)(v_s + (bloc * NO + o) * DOUT + dg * 4);
                        float2 tf = unpk(fma2(h1, vv.y, mul2(h0, vv.x)));
                        float t = tf.x + tf.y;
                        if (PASS == 2 && dg == 0)
                            t += g_blog[(size_t)(cur_bt * BT + bloc) * (NI * NO) + (size_t)n * NO + o];
                        t += __shfl_xor_sync(0xffffffffu, t, 1);
                        t += __shfl_xor_sync(0xffffffffu, t, 2);
                        if (PASS == 1 && dg == 0)
                            g_blog[(size_t)(cur_bt * BT + bloc) * (NI * NO) + (size_t)n * NO + o] = t;

                        float e = __expf(t);
                        ull ee = pack2(e, e);
                        t0[q] = mul2(ee, h0);
                        t1[q] = mul2(ee, h1);
                        float ws = e;
                        ws += __shfl_xor_sync(0xffffffffu, ws, 4);
                        ws += __shfl_xor_sync(0xffffffffu, ws, 8);
                        ws += __shfl_xor_sync(0xffffffffu, ws, 16);
                        if ((tid & 31) == 0) red[g * 64 + wg * 16 + q * 4 + wiw] = ws;
                    }
                    asm volatile("bar.sync %0, 128;" :: "r"(wg + 1) : "memory");
#pragma unroll
                    for (int q = 0; q < 4; q++) {
                        const int bi = g * 4 + q;
                        float4 r4 = *(const float4*)(red + g * 64 + wg * 16 + q * 4);
                        float rc = __fdividef(1.f, (r4.x + r4.y) + (r4.z + r4.w));
                        ull cc = pack2(rc, rc);
                        s0[bi] = fma2(cc, t0[q], s0[bi]);
                        s1[bi] = fma2(cc, t1[q], s1[bi]);
                    }
                }
            }
        }
    }

    // final flush
#pragma unroll
    for (int bi = 0; bi < 8; bi++) {
        float* p = g_s + (size_t)(cur_bt * BT + wg * 8 + bi) * 512 + o * 16 + dg * 4;
        float2 a = unpk(s0[bi]); float2 b = unpk(s1[bi]);
        atomicAdd(p + 0, a.x); atomicAdd(p + 1, a.y);
        atomicAdd(p + 2, b.x); atomicAdd(p + 3, b.y);
    }

    // last-CTA squash
    __threadfence();
    if (tid == 0) {
        unsigned t = atomicAdd(&g_ctr, 1u);
        s_last = (t == GRID - 1) ? 1 : 0;
    }
    __syncthreads();
    if (s_last) {
        __threadfence();
        do_squash(vout);
        if (tid == 0) g_ctr = 0;   // deterministic for graph replays
    }
}

extern "C" void kernel_launch(void* const* d_in, const int* in_sizes, int n_in,
                              void* d_out, int out_size)
{
    const float* X = (const float*)d_in[0];
    const float* W = (const float*)d_in[1];
    if (in_sizes[0] != BSZ * NI * DI) { X = (const float*)d_in[1]; W = (const float*)d_in[0]; }

    float* vdev = nullptr;
    cudaGetSymbolAddress((void**)&vdev, g_v);

    const int smem = 65536 + 8192 + 65536 + 512;   // 139776 B
    cudaFuncSetAttribute(caps_pass<0>, cudaFuncAttributeMaxDynamicSharedMemorySize, smem);
    cudaFuncSetAttribute(caps_pass<1>, cudaFuncAttributeMaxDynamicSharedMemorySize, smem);
    cudaFuncSetAttribute(caps_pass<2>, cudaFuncAttributeMaxDynamicSharedMemorySize, smem);

    caps_pass<0><<<GRID, NTHREADS, smem>>>(X, W, vdev);
    caps_pass<1><<<GRID, NTHREADS, smem>>>(X, W, vdev);
    caps_pass<2><<<GRID, NTHREADS, smem>>>(X, W, (float*)d_out);
}

// round 5
// speedup vs baseline: 1.1770x; 1.1770x over previous
#include <cuda_runtime.h>
#include <cstdint>
#include <cstddef>

#define BSZ   64
#define NI    2048
#define DI    8
#define NO    32
#define DOUT  16

#define BT    32
#define NCH   4
#define NTHREADS 512
#define GRID  148
#define ITEMS_PER_BT (NI / NCH)            // 512
#define N_ITEMS (ITEMS_PER_BT * 2)         // 1024

typedef unsigned long long ull;

__device__ float g_s[BSZ * NO * DOUT];           // zero at entry (squash re-zeros)
__device__ float g_v[BSZ * NO * DOUT];
__device__ float g_blog[(size_t)BSZ * NI * NO];  // 16 MB logits
__device__ unsigned g_ctr;                       // last-CTA ticket (reset each launch)

static __device__ __forceinline__ ull pack2(float lo, float hi) {
    ull r; asm("mov.b64 %0,{%1,%2};" : "=l"(r) : "f"(lo), "f"(hi)); return r;
}
static __device__ __forceinline__ float2 unpk(ull v) {
    float2 r; asm("mov.b64 {%0,%1},%2;" : "=f"(r.x), "=f"(r.y) : "l"(v)); return r;
}
static __device__ __forceinline__ ull fma2(ull a, ull b, ull c) {
    ull d; asm("fma.rn.f32x2 %0,%1,%2,%3;" : "=l"(d) : "l"(a), "l"(b), "l"(c)); return d;
}
static __device__ __forceinline__ ull mul2(ull a, ull b) {
    ull d; asm("mul.rn.f32x2 %0,%1,%2;" : "=l"(d) : "l"(a), "l"(b)); return d;
}

// Squash by the last CTA of each pass: v = s*||s||/(1+||s||^2), re-zero g_s.
static __device__ __forceinline__ void do_squash(float* __restrict__ dst)
{
#pragma unroll
    for (int rr = 0; rr < 4; rr++) {
        int row = threadIdx.x * 4 + rr;            // 2048 rows of 16
        const float* p = g_s + row * 16;
        float4 a = *(const float4*)(p + 0);
        float4 b = *(const float4*)(p + 4);
        float4 c = *(const float4*)(p + 8);
        float4 d = *(const float4*)(p + 12);
        float sq = a.x*a.x + a.y*a.y + a.z*a.z + a.w*a.w
                 + b.x*b.x + b.y*b.y + b.z*b.z + b.w*b.w
                 + c.x*c.x + c.y*c.y + c.z*c.z + c.w*c.w
                 + d.x*d.x + d.y*d.y + d.z*d.z + d.w*d.w;
        float f = sqrtf(sq) / (1.0f + sq);
        float* q = dst + row * 16;
        *(float4*)(q + 0)  = make_float4(a.x*f, a.y*f, a.z*f, a.w*f);
        *(float4*)(q + 4)  = make_float4(b.x*f, b.y*f, b.z*f, b.w*f);
        *(float4*)(q + 8)  = make_float4(c.x*f, c.y*f, c.z*f, c.w*f);
        *(float4*)(q + 12) = make_float4(d.x*f, d.y*f, d.z*f, d.w*f);
        float4 z = make_float4(0.f, 0.f, 0.f, 0.f);
        float* zp = g_s + row * 16;
        *(float4*)(zp + 0) = z; *(float4*)(zp + 4) = z;
        *(float4*)(zp + 8) = z; *(float4*)(zp + 12) = z;
    }
}

// W SMEM layout per n (16 KB): per o, 32 16B-units. Unit (o,dp,ip) holds the
// fma2 pairs (W[o,2dp,i],W[o,2dp+1,i]) for i in {2ip,2ip+1}, placed at unit
// index  o*32 + ((ip*8 + dp) ^ (o&1)).
// Bank-col = ((2dg+p) ^ (o&1)) mod 8 -> the 8 lanes of each LDS.128 phase
// (2 o's x 4 dg) hit 8 distinct columns: conflict-free. Same for staging STS.
template <int PASS>
__global__ void __launch_bounds__(NTHREADS, 1)
caps_pass(const float* __restrict__ X, const float* __restrict__ W,
          float* __restrict__ vout)
{
    extern __shared__ char sm[];
    char*   w_s = sm;                                  // NCH*16384 = 65536 B
    float2* x_d = (float2*)(sm + 65536);               // 8192 B (x dup pairs)
    float*  v_s = (float*)(sm + 65536 + 8192);         // 65536 B
    float*  red = (float*)(sm + 65536 + 8192 + 65536); // 512 B
    __shared__ int s_last;

    const int tid = threadIdx.x;
    const int wg  = tid >> 7;
    const int wt  = tid & 127;
    const int o   = wt >> 2;
    const int dg  = wt & 3;
    const int wiw = (wt >> 5) & 3;
    const unsigned osw = (unsigned)(o & 1);

    // staging coords: (o_s, dp_s, iq_s), one 8-float gmem chunk -> 2 units
    const int so  = tid >> 4;
    const int sdp = tid & 7;
    const int siq = (tid >> 3) & 1;
    const unsigned ssw = (unsigned)(so & 1);

    const ull Z = pack2(0.f, 0.f);
    ull s0[8], s1[8];
#pragma unroll
    for (int b = 0; b < 8; b++) { s0[b] = Z; s1[b] = Z; }

    int cur_bt = -1;

    for (int it = blockIdx.x; it < N_ITEMS; it += GRID) {
        const int btile = it >> 9;
        const int n0    = (it & (ITEMS_PER_BT - 1)) * NCH;

        if (btile != cur_bt) {
            __syncthreads();
            if (cur_bt >= 0) {
#pragma unroll
                for (int bi = 0; bi < 8; bi++) {
                    float* p = g_s + (size_t)(cur_bt * BT + wg * 8 + bi) * 512 + o * 16 + dg * 4;
                    float2 a = unpk(s0[bi]); float2 b = unpk(s1[bi]);
                    atomicAdd(p + 0, a.x); atomicAdd(p + 1, a.y);
                    atomicAdd(p + 2, b.x); atomicAdd(p + 3, b.y);
                    s0[bi] = Z; s1[bi] = Z;
                }
            }
            if (PASS > 0) {
#pragma unroll
                for (int k = 0; k < 8; k++) {
                    int f = k * 2048 + tid * 4;
                    *(float4*)(v_s + f) = *(const float4*)(g_v + (size_t)btile * BT * 512 + f);
                }
            }
            cur_bt = btile;
        } else {
            __syncthreads();
        }

        // ---- stage W for NCH n's ----
#pragma unroll
        for (int nn = 0; nn < NCH; nn++) {
            const float* gw = W + (size_t)(n0 + nn) * 4096 + so * 128 + (2 * sdp) * 8 + siq * 4;
            float4 a = *(const float4*)gw;        // d = 2*sdp,   i = 4iq..4iq+3
            float4 c = *(const float4*)(gw + 8);  // d = 2*sdp+1
            char* base = w_s + nn * 16384 + so * 512;
            unsigned u0 = ((unsigned)(2 * siq)     * 8 + (unsigned)sdp) ^ ssw;  // ip = 2iq
            unsigned u1 = ((unsigned)(2 * siq + 1) * 8 + (unsigned)sdp) ^ ssw;  // ip = 2iq+1
            *(float4*)(base + u0 * 16) = make_float4(a.x, c.x, a.y, c.y);
            *(float4*)(base + u1 * 16) = make_float4(a.z, c.z, a.w, c.w);
        }
        // ---- stage x duplicated pairs: x_d[b*32 + nn*8 + i] = (x,x) ----
        {
            int f = tid * 2;
            int bb = f >> 5, rem = f & 31;
            float2 t2 = *(const float2*)(X + (size_t)(cur_bt * BT + bb) * (NI * DI) + n0 * DI + rem);
            x_d[f]     = make_float2(t2.x, t2.x);
            x_d[f + 1] = make_float2(t2.y, t2.y);
        }
        __syncthreads();

#pragma unroll 1
        for (int nn = 0; nn < NCH; nn++) {
            const int n = n0 + nn;

            // 8 conflict-free LDS.128 -> 16 fma2 operand pairs
            ull w0[8], w1[8];
            const char* wb = w_s + nn * 16384 + o * 512;
#pragma unroll
            for (int ip = 0; ip < 4; ip++) {
                unsigned uA = ((unsigned)(ip * 8 + 2 * dg)     ) ^ osw;
                unsigned uB = ((unsigned)(ip * 8 + 2 * dg + 1) ) ^ osw;
                ulonglong2 A = *(const ulonglong2*)(wb + uA * 16);
                ulonglong2 B = *(const ulonglong2*)(wb + uB * 16);
                w0[2 * ip] = A.x; w0[2 * ip + 1] = A.y;
                w1[2 * ip] = B.x; w1[2 * ip + 1] = B.y;
            }

            if (PASS == 0) {
                const ull C = pack2(0.03125f, 0.03125f);
#pragma unroll
                for (int bi = 0; bi < 8; bi++) {
                    const ulonglong2* xq = (const ulonglong2*)(x_d + (wg * 8 + bi) * 32 + nn * 8);
                    ulonglong2 qa = xq[0];
                    ull h0 = fma2(w0[0], qa.x, mul2(w0[1], qa.y));
                    ull h1 = fma2(w1[0], qa.x, mul2(w1[1], qa.y));
                    ulonglong2 qb = xq[1];
                    h0 = fma2(w0[2], qb.x, h0); h1 = fma2(w1[2], qb.x, h1);
                    h0 = fma2(w0[3], qb.y, h0); h1 = fma2(w1[3], qb.y, h1);
                    ulonglong2 qc = xq[2];
                    h0 = fma2(w0[4], qc.x, h0); h1 = fma2(w1[4], qc.x, h1);
                    h0 = fma2(w0[5], qc.y, h0); h1 = fma2(w1[5], qc.y, h1);
                    ulonglong2 qd = xq[3];
                    h0 = fma2(w0[6], qd.x, h0); h1 = fma2(w1[6], qd.x, h1);
                    h0 = fma2(w0[7], qd.y, h0); h1 = fma2(w1[7], qd.y, h1);
                    s0[bi] = fma2(C, h0, s0[bi]);
                    s1[bi] = fma2(C, h1, s1[bi]);
                }
            } else {
#pragma unroll
                for (int g = 0; g < 2; g++) {
                    ull t0[4], t1[4];
#pragma unroll
                    for (int q = 0; q < 4; q++) {
                        const int bi = g * 4 + q, bloc = wg * 8 + bi;
                        const ulonglong2* xq = (const ulonglong2*)(x_d + bloc * 32 + nn * 8);
                        ulonglong2 qa = xq[0];
                        ull h0 = fma2(w0[0], qa.x, mul2(w0[1], qa.y));
                        ull h1 = fma2(w1[0], qa.x, mul2(w1[1], qa.y));
                        ulonglong2 qb = xq[1];
                        h0 = fma2(w0[2], qb.x, h0); h1 = fma2(w1[2], qb.x, h1);
                        h0 = fma2(w0[3], qb.y, h0); h1 = fma2(w1[3], qb.y, h1);
                        ulonglong2 qc = xq[2];
                        h0 = fma2(w0[4], qc.x, h0); h1 = fma2(w1[4], qc.x, h1);
                        h0 = fma2(w0[5], qc.y, h0); h1 = fma2(w1[5], qc.y, h1);
                        ulonglong2 qd = xq[3];
                        h0 = fma2(w0[6], qd.x, h0); h1 = fma2(w1[6], qd.x, h1);
                        h0 = fma2(w0[7], qd.y, h0); h1 = fma2(w1[7], qd.y, h1);

                        const ulonglong2 vv = *(const ulonglong2*)(v_s + (bloc * NO + o) * DOUT + dg * 4);
                        float2 tf = unpk(fma2(h1, vv.y, mul2(h0, vv.x)));
                        float t = tf.x + tf.y;
                        if (PASS == 2 && dg == 0)
                            t += g_blog[(size_t)(cur_bt * BT + bloc) * (NI * NO) + (size_t)n * NO + o];
                        t += __shfl_xor_sync(0xffffffffu, t, 1);
                        t += __shfl_xor_sync(0xffffffffu, t, 2);
                        if (PASS == 1 && dg == 0)
                            g_blog[(size_t)(cur_bt * BT + bloc) * (NI * NO) + (size_t)n * NO + o] = t;

                        float e = __expf(t);
                        ull ee = pack2(e, e);
                        t0[q] = mul2(ee, h0);
                        t1[q] = mul2(ee, h1);
                        float ws = e;
                        ws += __shfl_xor_sync(0xffffffffu, ws, 4);
                        ws += __shfl_xor_sync(0xffffffffu, ws, 8);
                        ws += __shfl_xor_sync(0xffffffffu, ws, 16);
                        if ((tid & 31) == 0) red[g * 64 + wg * 16 + q * 4 + wiw] = ws;
                    }
                    asm volatile("bar.sync %0, 128;" :: "r"(wg + 1) : "memory");
#pragma unroll
                    for (int q = 0; q < 4; q++) {
                        const int bi = g * 4 + q;
                        float4 r4 = *(const float4*)(red + g * 64 + wg * 16 + q * 4);
                        float rc = __fdividef(1.f, (r4.x + r4.y) + (r4.z + r4.w));
                        ull cc = pack2(rc, rc);
                        s0[bi] = fma2(cc, t0[q], s0[bi]);
                        s1[bi] = fma2(cc, t1[q], s1[bi]);
                    }
                }
            }
        }
    }

    // final flush
#pragma unroll
    for (int bi = 0; bi < 8; bi++) {
        float* p = g_s + (size_t)(cur_bt * BT + wg * 8 + bi) * 512 + o * 16 + dg * 4;
        float2 a = unpk(s0[bi]); float2 b = unpk(s1[bi]);
        atomicAdd(p + 0, a.x); atomicAdd(p + 1, a.y);
        atomicAdd(p + 2, b.x); atomicAdd(p + 3, b.y);
    }

    // last-CTA squash
    __threadfence();
    if (tid == 0) {
        unsigned t = atomicAdd(&g_ctr, 1u);
        s_last = (t == GRID - 1) ? 1 : 0;
    }
    __syncthreads();
    if (s_last) {
        __threadfence();
        do_squash(vout);
        if (tid == 0) g_ctr = 0;   // deterministic across graph replays
    }
}

extern "C" void kernel_launch(void* const* d_in, const int* in_sizes, int n_in,
                              void* d_out, int out_size)
{
    const float* X = (const float*)d_in[0];
    const float* W = (const float*)d_in[1];
    if (in_sizes[0] != BSZ * NI * DI) { X = (const float*)d_in[1]; W = (const float*)d_in[0]; }

    float* vdev = nullptr;
    cudaGetSymbolAddress((void**)&vdev, g_v);

    const int smem = 65536 + 8192 + 65536 + 512;   // 139776 B
    cudaFuncSetAttribute(caps_pass<0>, cudaFuncAttributeMaxDynamicSharedMemorySize, smem);
    cudaFuncSetAttribute(caps_pass<1>, cudaFuncAttributeMaxDynamicSharedMemorySize, smem);
    cudaFuncSetAttribute(caps_pass<2>, cudaFuncAttributeMaxDynamicSharedMemorySize, smem);

    caps_pass<0><<<GRID, NTHREADS, smem>>>(X, W, vdev);
    caps_pass<1><<<GRID, NTHREADS, smem>>>(X, W, vdev);
    caps_pass<2><<<GRID, NTHREADS, smem>>>(X, W, (float*)d_out);
}